// round 10
// baseline (speedup 1.0000x reference)
#include <cuda_runtime.h>
#include <cuda_fp16.h>

// 5-level db4 DWT, symmetric extension. fp16 smem cascade (fp32 scalar FMA),
// 4 outputs/thread from 2 conflict-free aligned LDS.128.
// TWO rows per 256-thread CTA: threads 0-127 -> row 2b, 128-255 -> row 2b+1,
// private smem per half. Combines NT=128's low pass-quantization waste with
// NT=256-class occupancy (28.8KB/CTA -> 7 CTAs/SM, 56 warps).

#define NROWS 4096
#define NT    256
#define LNT   128   // threads per row half

#define L0 4096
#define L1 2051
#define L2 1029
#define L3 518
#define L4 262
#define L5 134

#define O_APPROX 0
#define O_D5 (NROWS * L5)
#define O_D4 (O_D5 + NROWS * L5)
#define O_D3 (O_D4 + NROWS * L4)
#define O_D2 (O_D3 + NROWS * L3)
#define O_D1 (O_D2 + NROWS * L2)

// Reversed filters: y[j] = sum_r RF[r] * ext[2j + r]
#define RLO0  0.23037781330885523f
#define RLO1  0.7148465705525415f
#define RLO2  0.6308807679295904f
#define RLO3 -0.02798376941698385f
#define RLO4 -0.18703481171888114f
#define RLO5  0.030841381835986965f
#define RLO6  0.032883011666982945f
#define RLO7 -0.010597401784997278f

#define RHI0 -0.010597401784997278f
#define RHI1 -0.032883011666982945f
#define RHI2  0.030841381835986965f
#define RHI3  0.18703481171888114f
#define RHI4 -0.02798376941698385f
#define RHI5 -0.6308807679295904f
#define RHI6  0.7148465705525415f
#define RHI7 -0.23037781330885523f

__device__ __forceinline__ int coff(int s) { return ((2 * s + 4) & 7) + 6; }

// One level. q: fp16 buffer, ext[i] = q[c+i], input length N, M=(N+7)/2 outputs.
// cD -> fp32 gmem (STG.128 via sigma shift). Non-LAST: cA -> fp16 buffer qn
// (ext base cn) incl. mirror pads. LAST: cA -> fp32 gmem cAg (same sigma).
template<bool LAST>
__device__ __forceinline__ void dwt16(const __half* __restrict__ q, int c,
                                      int N, int sigma,
                                      __half* __restrict__ qn, int cn,
                                      float* __restrict__ cD,
                                      float* __restrict__ cAg, int tid)
{
    const int M  = (N + 7) >> 1;
    const int NB = (M + sigma + 3) >> 2;
    for (int T = tid; T < NB; T += LNT) {
        const int j0 = 4 * T - sigma;
        const int h0 = c + 8 * T - 2 * sigma - 2;   // ≡ 0 (mod 8) by choice of c
        const uint4 u0 = *reinterpret_cast<const uint4*>(q + h0);
        const uint4 u1 = *reinterpret_cast<const uint4*>(q + h0 + 8);

        float w[14];
        {
            const __half2* ha = reinterpret_cast<const __half2*>(&u0);
            const __half2* hb = reinterpret_cast<const __half2*>(&u1);
            float2 t;
            t = __half22float2(ha[1]); w[0]  = t.x; w[1]  = t.y;
            t = __half22float2(ha[2]); w[2]  = t.x; w[3]  = t.y;
            t = __half22float2(ha[3]); w[4]  = t.x; w[5]  = t.y;
            t = __half22float2(hb[0]); w[6]  = t.x; w[7]  = t.y;
            t = __half22float2(hb[1]); w[8]  = t.x; w[9]  = t.y;
            t = __half22float2(hb[2]); w[10] = t.x; w[11] = t.y;
            t = __half22float2(hb[3]); w[12] = t.x; w[13] = t.y;
        }

        float lo[4], hi[4];
#pragma unroll
        for (int m = 0; m < 4; m++) {
            float l = RLO0 * w[2 * m];
            l = fmaf(RLO1, w[2 * m + 1], l);
            l = fmaf(RLO2, w[2 * m + 2], l);
            l = fmaf(RLO3, w[2 * m + 3], l);
            l = fmaf(RLO4, w[2 * m + 4], l);
            l = fmaf(RLO5, w[2 * m + 5], l);
            l = fmaf(RLO6, w[2 * m + 6], l);
            l = fmaf(RLO7, w[2 * m + 7], l);
            lo[m] = l;
            float h = RHI0 * w[2 * m];
            h = fmaf(RHI1, w[2 * m + 1], h);
            h = fmaf(RHI2, w[2 * m + 2], h);
            h = fmaf(RHI3, w[2 * m + 3], h);
            h = fmaf(RHI4, w[2 * m + 4], h);
            h = fmaf(RHI5, w[2 * m + 5], h);
            h = fmaf(RHI6, w[2 * m + 6], h);
            h = fmaf(RHI7, w[2 * m + 7], h);
            hi[m] = h;
        }

        const bool interior = (j0 >= 0) && (j0 + 4 <= M);
        if (interior) {
            *reinterpret_cast<float4*>(cD + j0) =
                make_float4(hi[0], hi[1], hi[2], hi[3]);
            if (LAST)
                *reinterpret_cast<float4*>(cAg + j0) =
                    make_float4(lo[0], lo[1], lo[2], lo[3]);
        } else {
#pragma unroll
            for (int m = 0; m < 4; m++) {
                const int j = j0 + m;
                if (j >= 0 && j < M) {
                    cD[j] = hi[m];
                    if (LAST) cAg[j] = lo[m];
                }
            }
        }

        if (!LAST) {
            if (interior && j0 > 5 && j0 + 3 < M - 8) {
#pragma unroll
                for (int m = 0; m < 4; m++)
                    qn[cn + 6 + j0 + m] = __float2half_rn(lo[m]);
            } else {
#pragma unroll
                for (int m = 0; m < 4; m++) {
                    const int j = j0 + m;
                    if (j < 0 || j >= M) continue;
                    const __half v = __float2half_rn(lo[m]);
                    qn[cn + 6 + j] = v;                      // interior
                    if (j <= 5)      qn[cn + 5 - j] = v;     // left mirror
                    if (j >= M - 8)  qn[cn + 2 * M + 5 - j] = v; // right mirror
                }
            }
        }
    }
}

__global__ __launch_bounds__(NT)
void wavelet5_kernel(const float* __restrict__ x, float* __restrict__ out) {
    __shared__ __align__(16) __half IN16[2][4160];
    __shared__ __align__(16) __half A16[2][2112];
    __shared__ __align__(16) __half B16[2][1088];

    const int half = threadIdx.x >> 7;      // 0 or 1: which row of the pair
    const int tid  = threadIdx.x & (LNT - 1);
    const int row  = 2 * blockIdx.x + half;

    __half* __restrict__ IN = IN16[half];
    __half* __restrict__ AA = A16[half];
    __half* __restrict__ BB = B16[half];

    // Per-level gmem alignment shifts (floats mod 4 of each cD row base)
    const int s1 = (3 * row) & 3;   // L1=2051 ≡ 3 (mod 4)
    const int s2 = row & 3;         // L2=1029 ≡ 1
    const int s3 = (2 * row) & 3;   // L3,L4,L5 ≡ 2
    const int c1 = coff(s1), c2 = coff(s2), c3 = coff(s3);

    const float* __restrict__ xr = x + (size_t)row * L0;

    // Build fp16 extended input: ext[i] = IN[c1+i]
    {
        const float4* __restrict__ x4 = reinterpret_cast<const float4*>(xr);
        __half2* __restrict__ dst = reinterpret_cast<__half2*>(IN + c1 + 6);
#pragma unroll 4
        for (int u = tid; u < L0 / 4; u += LNT) {
            const float4 v = x4[u];
            dst[2 * u]     = __floats2half2_rn(v.x, v.y);
            dst[2 * u + 1] = __floats2half2_rn(v.z, v.w);
        }
        if (tid < 6) {
            IN[c1 + tid] = __float2half_rn(xr[5 - tid]);            // left ext
        } else if (tid < 14) {
            const int t = tid - 6;
            IN[c1 + L0 + 6 + t] = __float2half_rn(xr[L0 - 1 - t]);  // right ext
        }
    }
    __syncthreads();

    float* __restrict__ d1 = out + O_D1 + (size_t)row * L1;
    float* __restrict__ d2 = out + O_D2 + (size_t)row * L2;
    float* __restrict__ d3 = out + O_D3 + (size_t)row * L3;
    float* __restrict__ d4 = out + O_D4 + (size_t)row * L4;
    float* __restrict__ d5 = out + O_D5 + (size_t)row * L5;
    float* __restrict__ ap = out + O_APPROX + (size_t)row * L5;

    dwt16<false>(IN, c1, L0, s1, AA, c2, d1, nullptr, tid);  // 4096 -> 2051
    __syncthreads();
    dwt16<false>(AA, c2, L1, s2, BB, c3, d2, nullptr, tid);  // 2051 -> 1029
    __syncthreads();
    dwt16<false>(BB, c3, L2, s3, IN, c3, d3, nullptr, tid);  // 1029 -> 518
    __syncthreads();
    dwt16<false>(IN, c3, L3, s3, AA, c3, d4, nullptr, tid);  // 518  -> 262
    __syncthreads();
    dwt16<true>(AA, c3, L4, s3, nullptr, 0, d5, ap, tid);    // 262  -> 134
}

extern "C" void kernel_launch(void* const* d_in, const int* in_sizes, int n_in,
                              void* d_out, int out_size) {
    const float* x = (const float*)d_in[0];
    float* out = (float*)d_out;
    (void)in_sizes; (void)n_in; (void)out_size;
    wavelet5_kernel<<<NROWS / 2, NT>>>(x, out);
}

// round 11
// speedup vs baseline: 1.1212x; 1.1212x over previous
#include <cuda_runtime.h>
#include <cuda_fp16.h>

// 5-level db4 DWT, symmetric extension. Level 1 computed DIRECTLY from gmem
// (fp32 windows, 4 aligned LDG.128/unit, scalar reflect at boundaries) —
// no input staging pass, no barrier, no fp16 round-trip for level 1.
// Levels 2-5: fp16 smem cascade (R5 hot loop), ping-pong A16/B16 (6.3KB/CTA).

#define NROWS 4096
#define NT    256

#define L0 4096
#define L1 2051
#define L2 1029
#define L3 518
#define L4 262
#define L5 134

#define O_APPROX 0
#define O_D5 (NROWS * L5)
#define O_D4 (O_D5 + NROWS * L5)
#define O_D3 (O_D4 + NROWS * L4)
#define O_D2 (O_D3 + NROWS * L3)
#define O_D1 (O_D2 + NROWS * L2)

// Reversed filters: y[j] = sum_r RF[r] * ext[2j + r]
#define RLO0  0.23037781330885523f
#define RLO1  0.7148465705525415f
#define RLO2  0.6308807679295904f
#define RLO3 -0.02798376941698385f
#define RLO4 -0.18703481171888114f
#define RLO5  0.030841381835986965f
#define RLO6  0.032883011666982945f
#define RLO7 -0.010597401784997278f

#define RHI0 -0.010597401784997278f
#define RHI1 -0.032883011666982945f
#define RHI2  0.030841381835986965f
#define RHI3  0.18703481171888114f
#define RHI4 -0.02798376941698385f
#define RHI5 -0.6308807679295904f
#define RHI6  0.7148465705525415f
#define RHI7 -0.23037781330885523f

__device__ __forceinline__ int coff(int s) { return ((2 * s + 4) & 7) + 6; }

__device__ __forceinline__ void taps8(const float* w, float& l, float& h) {
    l = RLO0 * w[0];
    l = fmaf(RLO1, w[1], l); l = fmaf(RLO2, w[2], l);
    l = fmaf(RLO3, w[3], l); l = fmaf(RLO4, w[4], l);
    l = fmaf(RLO5, w[5], l); l = fmaf(RLO6, w[6], l);
    l = fmaf(RLO7, w[7], l);
    h = RHI0 * w[0];
    h = fmaf(RHI1, w[1], h); h = fmaf(RHI2, w[2], h);
    h = fmaf(RHI3, w[3], h); h = fmaf(RHI4, w[4], h);
    h = fmaf(RHI5, w[5], h); h = fmaf(RHI6, w[6], h);
    h = fmaf(RHI7, w[7], h);
}

// Level 1 straight from gmem. Window w[k] = x_sym[2*j0 - 6 + k], j0 = 4T - s1.
// Interior: 4 aligned LDG.128 starting at base = 8T - 2*s1 - 6 - DELTA.
template<int DELTA>
__device__ __forceinline__ void lvl1_gmem(const float* __restrict__ xr, int s1,
                                          __half* __restrict__ qn, int cn,
                                          float* __restrict__ cD, int tid) {
    const int M = L1;
    const int NB = (M + s1 + 3) >> 2;
    for (int T = tid; T < NB; T += NT) {
        const int j0 = 4 * T - s1;
        const int base = 8 * T - 2 * s1 - 6 - DELTA;   // ≡ 0 (mod 4)

        float X[16];
        if (base >= 0 && base <= L0 - 16) {
            const float4* __restrict__ xx =
                reinterpret_cast<const float4*>(xr + base);
            const float4 a = xx[0], b = xx[1], c = xx[2], d = xx[3];
            X[0] = a.x;  X[1] = a.y;  X[2] = a.z;  X[3] = a.w;
            X[4] = b.x;  X[5] = b.y;  X[6] = b.z;  X[7] = b.w;
            X[8] = c.x;  X[9] = c.y;  X[10] = c.z; X[11] = c.w;
            X[12] = d.x; X[13] = d.y; X[14] = d.z; X[15] = d.w;
        } else {
#pragma unroll
            for (int k = 0; k < 14; k++) {
                int idx = base + DELTA + k;
                idx = (idx < 0) ? (-1 - idx) : idx;
                idx = (idx >= L0) ? (2 * L0 - 1 - idx) : idx;
                X[DELTA + k] = xr[idx];
            }
        }
        const float* w = X + DELTA;

        float lo[4], hi[4];
#pragma unroll
        for (int m = 0; m < 4; m++) taps8(w + 2 * m, lo[m], hi[m]);

        const bool interior = (j0 >= 0) && (j0 + 4 <= M);
        if (interior) {
            *reinterpret_cast<float4*>(cD + j0) =
                make_float4(hi[0], hi[1], hi[2], hi[3]);
        } else {
#pragma unroll
            for (int m = 0; m < 4; m++) {
                const int j = j0 + m;
                if (j >= 0 && j < M) cD[j] = hi[m];
            }
        }

        if (interior && j0 > 5 && j0 + 3 < M - 8) {
#pragma unroll
            for (int m = 0; m < 4; m++)
                qn[cn + 6 + j0 + m] = __float2half_rn(lo[m]);
        } else {
#pragma unroll
            for (int m = 0; m < 4; m++) {
                const int j = j0 + m;
                if (j < 0 || j >= M) continue;
                const __half v = __float2half_rn(lo[m]);
                qn[cn + 6 + j] = v;                          // interior
                if (j <= 5)      qn[cn + 5 - j] = v;         // left mirror
                if (j >= M - 8)  qn[cn + 2 * M + 5 - j] = v; // right mirror
            }
        }
    }
}

// Levels 2-5 (R5 hot loop). q: fp16 buffer, ext[i]=q[c+i], N in, M=(N+7)/2 out.
template<bool LAST>
__device__ __forceinline__ void dwt16(const __half* __restrict__ q, int c,
                                      int N, int sigma,
                                      __half* __restrict__ qn, int cn,
                                      float* __restrict__ cD,
                                      float* __restrict__ cAg, int tid)
{
    const int M  = (N + 7) >> 1;
    const int NB = (M + sigma + 3) >> 2;
    for (int T = tid; T < NB; T += NT) {
        const int j0 = 4 * T - sigma;
        const int h0 = c + 8 * T - 2 * sigma - 2;   // ≡ 0 (mod 8)
        const uint4 u0 = *reinterpret_cast<const uint4*>(q + h0);
        const uint4 u1 = *reinterpret_cast<const uint4*>(q + h0 + 8);

        float w[14];
        {
            const __half2* ha = reinterpret_cast<const __half2*>(&u0);
            const __half2* hb = reinterpret_cast<const __half2*>(&u1);
            float2 t;
            t = __half22float2(ha[1]); w[0]  = t.x; w[1]  = t.y;
            t = __half22float2(ha[2]); w[2]  = t.x; w[3]  = t.y;
            t = __half22float2(ha[3]); w[4]  = t.x; w[5]  = t.y;
            t = __half22float2(hb[0]); w[6]  = t.x; w[7]  = t.y;
            t = __half22float2(hb[1]); w[8]  = t.x; w[9]  = t.y;
            t = __half22float2(hb[2]); w[10] = t.x; w[11] = t.y;
            t = __half22float2(hb[3]); w[12] = t.x; w[13] = t.y;
        }

        float lo[4], hi[4];
#pragma unroll
        for (int m = 0; m < 4; m++) taps8(w + 2 * m, lo[m], hi[m]);

        const bool interior = (j0 >= 0) && (j0 + 4 <= M);
        if (interior) {
            *reinterpret_cast<float4*>(cD + j0) =
                make_float4(hi[0], hi[1], hi[2], hi[3]);
            if (LAST)
                *reinterpret_cast<float4*>(cAg + j0) =
                    make_float4(lo[0], lo[1], lo[2], lo[3]);
        } else {
#pragma unroll
            for (int m = 0; m < 4; m++) {
                const int j = j0 + m;
                if (j >= 0 && j < M) {
                    cD[j] = hi[m];
                    if (LAST) cAg[j] = lo[m];
                }
            }
        }

        if (!LAST) {
            if (interior && j0 > 5 && j0 + 3 < M - 8) {
#pragma unroll
                for (int m = 0; m < 4; m++)
                    qn[cn + 6 + j0 + m] = __float2half_rn(lo[m]);
            } else {
#pragma unroll
                for (int m = 0; m < 4; m++) {
                    const int j = j0 + m;
                    if (j < 0 || j >= M) continue;
                    const __half v = __float2half_rn(lo[m]);
                    qn[cn + 6 + j] = v;                          // interior
                    if (j <= 5)      qn[cn + 5 - j] = v;         // left mirror
                    if (j >= M - 8)  qn[cn + 2 * M + 5 - j] = v; // right mirror
                }
            }
        }
    }
}

__global__ __launch_bounds__(NT, 7)
void wavelet5_kernel(const float* __restrict__ x, float* __restrict__ out) {
    __shared__ __align__(16) __half A16[2112];  // lvl1 out / lvl2 in / lvl3 out / lvl4 in
    __shared__ __align__(16) __half B16[1088];  // lvl2 out / lvl3 in / lvl4 out / lvl5 in

    const int row = blockIdx.x;
    const int tid = threadIdx.x;

    const int s1 = (3 * row) & 3;   // L1=2051 ≡ 3 (mod 4)
    const int s2 = row & 3;         // L2=1029 ≡ 1
    const int s3 = (2 * row) & 3;   // L3,L4,L5 ≡ 2
    const int c2 = coff(s2), c3 = coff(s3);
    const int delta = (2 * s1 + 2) & 3;   // 0 or 2

    const float* __restrict__ xr = x + (size_t)row * L0;

    float* __restrict__ d1 = out + O_D1 + (size_t)row * L1;
    float* __restrict__ d2 = out + O_D2 + (size_t)row * L2;
    float* __restrict__ d3 = out + O_D3 + (size_t)row * L3;
    float* __restrict__ d4 = out + O_D4 + (size_t)row * L4;
    float* __restrict__ d5 = out + O_D5 + (size_t)row * L5;
    float* __restrict__ ap = out + O_APPROX + (size_t)row * L5;

    if (delta == 0) lvl1_gmem<0>(xr, s1, A16, c2, d1, tid);   // 4096 -> 2051
    else            lvl1_gmem<2>(xr, s1, A16, c2, d1, tid);
    __syncthreads();
    dwt16<false>(A16, c2, L1, s2, B16, c3, d2, nullptr, tid); // 2051 -> 1029
    __syncthreads();
    dwt16<false>(B16, c3, L2, s3, A16, c3, d3, nullptr, tid); // 1029 -> 518
    __syncthreads();
    dwt16<false>(A16, c3, L3, s3, B16, c3, d4, nullptr, tid); // 518  -> 262
    __syncthreads();
    dwt16<true>(B16, c3, L4, s3, nullptr, 0, d5, ap, tid);    // 262  -> 134
}

extern "C" void kernel_launch(void* const* d_in, const int* in_sizes, int n_in,
                              void* d_out, int out_size) {
    const float* x = (const float*)d_in[0];
    float* out = (float*)d_out;
    (void)in_sizes; (void)n_in; (void)out_size;
    wavelet5_kernel<<<NROWS, NT>>>(x, out);
}